// round 9
// baseline (speedup 1.0000x reference)
#include <cuda_runtime.h>
#include <cuda_bf16.h>

#define B_  256
#define T_  2048
#define BT  (B_ * T_)
#define NBLK 152

__device__ float4 g_pp[BT + 8 * B_];   // (10*pet, 0.5*pet, p-pet, 0) [t][b], padded
__device__ float4 g_w[(T_ / 2) * B_];  // (wu0,wd0,wu1,wd1) per t-pair [t/2][b]
__device__ float  g_params[BT * 8];    // row-major [r][8]
__device__ uint2  g_W1p[32 * 32];
__device__ uint2  g_W2p[16 * 8 * 32];
__device__ uint2  g_W3p[4 * 32];

__device__ __forceinline__ float tanhA(float x) {
    float r; asm("tanh.approx.f32 %0, %1;" : "=f"(r) : "f"(x)); return r;
}
__device__ __forceinline__ float heav(float x10) {   // h given 10*x
    return fmaf(0.5f, tanhA(x10), 0.5f);
}
__device__ __forceinline__ float sigm1(float x) {
    return fmaf(0.5f, tanhA(0.5f * x), 0.5f);
}
__device__ __forceinline__ unsigned int packbf(float lo, float hi) {
    unsigned int r;
    asm("cvt.rn.bf16x2.f32 %0, %1, %2;" : "=r"(r) : "f"(hi), "f"(lo));
    return r;
}
__device__ __forceinline__ void mma16816(float& c0, float& c1, float& c2, float& c3,
                                         unsigned int a0, unsigned int a1,
                                         unsigned int a2, unsigned int a3,
                                         unsigned int b0, unsigned int b1) {
    asm volatile(
        "mma.sync.aligned.m16n8k16.row.col.f32.bf16.bf16.f32 "
        "{%0,%1,%2,%3},{%4,%5,%6,%7},{%8,%9},{%0,%1,%2,%3};\n"
        : "+f"(c0), "+f"(c1), "+f"(c2), "+f"(c3)
        : "r"(a0), "r"(a1), "r"(a2), "r"(a3), "r"(b0), "r"(b1));
}

// ---- prep: stage scan inputs + pack weights -----------------------------------
__global__ void prep_kernel(const float* __restrict__ in,
                            const float* __restrict__ w1,
                            const float* __restrict__ w2,
                            const float* __restrict__ w3) {
    int bid = blockIdx.x;
    if (bid < 2048) {
        int r = bid * 256 + threadIdx.x;       // r = b*T + t
        int b = r >> 11;
        int t = r & 2047;
        float4 q = reinterpret_cast<const float4*>(in)[r * 5];   // cols 0..3
        g_pp[t * B_ + b] = make_float4(10.0f * q.x, 0.5f * q.x, q.z - q.x, 0.0f);
        return;
    }
    int tid = threadIdx.x;
    for (int i = tid; i < 32 * 32; i += 256) {           // W1 (15x256), k-pad to 16
        int lane = i & 31, nt = i >> 5;
        int g = lane >> 2, tig = lane & 3;
        int n = nt * 8 + g;
        float e0 = w1[(2 * tig) * 256 + n];
        float e1 = w1[(2 * tig + 1) * 256 + n];
        int k2 = 2 * tig + 8, k3 = 2 * tig + 9;
        float e2 = (k2 < 15) ? w1[k2 * 256 + n] : 0.0f;
        float e3 = (k3 < 15) ? w1[k3 * 256 + n] : 0.0f;
        g_W1p[i] = make_uint2(packbf(e0, e1), packbf(e2, e3));
    }
    for (int i = tid; i < 16 * 8 * 32; i += 256) {       // W2 (256x64)
        int lane = i & 31;
        int nt = (i >> 5) & 7;
        int kc = i >> 8;
        int g = lane >> 2, tig = lane & 3;
        int n = nt * 8 + g;
        int k0 = kc * 16 + 2 * tig;
        g_W2p[i] = make_uint2(packbf(w2[k0 * 64 + n], w2[(k0 + 1) * 64 + n]),
                              packbf(w2[(k0 + 8) * 64 + n], w2[(k0 + 9) * 64 + n]));
    }
    for (int i = tid; i < 4 * 32; i += 256) {            // W3 (64x8)
        int lane = i & 31;
        int kc = i >> 5;
        int g = lane >> 2, tig = lane & 3;
        int k0 = kc * 16 + 2 * tig;
        g_W3p[i] = make_uint2(packbf(w3[k0 * 8 + g], w3[(k0 + 1) * 8 + g]),
                              packbf(w3[(k0 + 8) * 8 + g], w3[(k0 + 9) * 8 + g]));
    }
}

// ===== scan stage macros (R7 pipeline, parameterized by basin S in {0,1}) =====
#define S_B2(S)                                                            \
  { float t3     = tanhA(fmaf(-10.0f, wd[S], y10B[S]));                    \
    float inner2 = fmaf(t3, wd[S] - yB[S], wd[S] + yB[S]);                 \
    wd[S] = fmaf(-vB[S], inner2, wd[S] + sd2B[S]); }

#define S_B1(S)                                                            \
  { float tw    = tanhA(fmaf(-10.0f, wl[S], rp10A[S]));                    \
    float inner = fmaf(tw, wl[S] - rpA[S], wl[S] + rpA[S]);                \
    float et2   = uA[S] * inner;                                           \
    wl[S] = fmaf(-uA[S], inner, wl[S] + ppvzA[S]);                         \
    float y   = rpA[S] - et2;                                              \
    float yt  = 10.0f * y;                                                 \
    vB[S]  = fmaf(0.25f, tanhA(yt), 0.25f);                                \
    yB[S] = y; y10B[S] = yt; sd2B[S] = ppvzA[S] - et2; }

#define S_A(S, QQ)                                                         \
  { float t1   = tanhA(fmaf(-10.0f, wu[S], (QQ).x));                       \
    float hd1  = fmaf(-0.5f, wu[S], (QQ).y);                               \
    float z    = fmaf(t1, hd1, hd1);                                       \
    float wuN  = (wu[S] + (QQ).z) + z;                                     \
    float tz   = tanhA(10.0f * z);                                         \
    float hz   = 0.5f * z;                                                 \
    float rp   = fmaf(tz, hz, hz);                                         \
    float rpt  = 10.0f * rp;                                               \
    uA[S]  = fmaf(0.25f, tanhA(rpt), 0.25f);                               \
    rpA[S] = rp; rp10A[S] = rpt; ppvzA[S] = (QQ).z + z;                    \
    wuS3[S] = wuS2[S]; wuS2[S] = wuS1[S]; wuS1[S] = wuN; wu[S] = wuN; }

#define BODY_NS(I, SLOT)                                                   \
  { float4 qa = qA[SLOT], qb = qB[SLOT];                                   \
    qA[SLOT] = pp[((I) + 6) * B_];                                         \
    qB[SLOT] = pp[((I) + 6) * B_ + 128];                                   \
    S_B2(0) S_B2(1)                                                        \
    S_B1(0) S_B1(1)                                                        \
    S_A(0, qa) S_A(1, qb) }

#define BODY_ST(I, SLOT)                                                   \
  { float4 qa = qA[SLOT], qb = qB[SLOT];                                   \
    qA[SLOT] = pp[((I) + 6) * B_];                                         \
    qB[SLOT] = pp[((I) + 6) * B_ + 128];                                   \
    float wdPa = wd[0], wdPb = wd[1];                                      \
    S_B2(0) S_B2(1)                                                        \
    wpa[(((I) - 2) >> 1) * B_] = make_float4(wuS3[0], wdPa, wuS2[0], wd[0]); \
    wpb[(((I) - 2) >> 1) * B_] = make_float4(wuS3[1], wdPb, wuS2[1], wd[1]); \
    S_B1(0) S_B1(1)                                                        \
    S_A(0, qa) S_A(1, qb) }

// ---- fused persistent kernel: 1 block/SM -------------------------------------
// block 0: scan, 128 threads x 2 basins each (1 warp/SMSP, 2 chains/thread)
// blocks 1..151: persistent MLP
__global__ void __launch_bounds__(256)
main_kernel(const float* __restrict__ in,
            const float* __restrict__ b1v,
            const float* __restrict__ b2v,
            const float* __restrict__ b3v) {
    __shared__ uint2 sW1[32 * 32];
    __shared__ uint2 sW2[16 * 8 * 32];
    __shared__ uint2 sW3[4 * 32];
    __shared__ float sB1[256];
    __shared__ float sB2[64];
    __shared__ float sB3[8];

    if (blockIdx.x == 0) {
        if (threadIdx.x >= 128) return;
        int b0 = threadIdx.x;                         // basins b0 and b0+128
        const float4* __restrict__ pp = g_pp + b0;
        float4* __restrict__ wpa = g_w + b0;
        float4* __restrict__ wpb = g_w + b0 + 128;

        float wu[2]   = {0.f, 0.f}, wl[2] = {0.f, 0.f}, wd[2] = {0.f, 0.f};
        float wuS1[2] = {0.f, 0.f}, wuS2[2] = {0.f, 0.f}, wuS3[2] = {0.f, 0.f};
        float rpA[2]  = {0.f, 0.f}, rp10A[2] = {0.f, 0.f};
        float uA[2]   = {0.25f, 0.25f}, ppvzA[2] = {0.f, 0.f};
        float yB[2]   = {0.f, 0.f}, y10B[2] = {0.f, 0.f};
        float vB[2]   = {0.25f, 0.25f}, sd2B[2] = {0.f, 0.f};

        float4 qA[6], qB[6];
#pragma unroll
        for (int s = 0; s < 6; ++s) {
            qA[s] = pp[s * B_];
            qB[s] = pp[s * B_ + 128];
        }

        // prologue: body 0 (A), body 1 (B1 + A)
        { float4 qa = qA[0], qb = qB[0];
          qA[0] = pp[6 * B_]; qB[0] = pp[6 * B_ + 128];
          S_A(0, qa) S_A(1, qb) }
        { float4 qa = qA[1], qb = qB[1];
          qA[1] = pp[7 * B_]; qB[1] = pp[7 * B_ + 128];
          S_B1(0) S_B1(1)
          S_A(0, qa) S_A(1, qb) }

        // main: bodies 2..2047  (341 groups of 6; store at odd bodies)
        for (int i = 2; i < T_; i += 6) {
            BODY_NS(i + 0, 2);
            BODY_ST(i + 1, 3);
            BODY_NS(i + 2, 4);
            BODY_ST(i + 3, 5);
            BODY_NS(i + 4, 0);
            BODY_ST(i + 5, 1);
        }

        // drain: wd(2046), wl(2047), wd(2047), final pair store
        S_B2(0) S_B2(1)
        float wd46a = wd[0], wd46b = wd[1];
        S_B1(0) S_B1(1)
        S_B2(0) S_B2(1)
        wpa[1023 * B_] = make_float4(wuS2[0], wd46a, wuS1[0], wd[0]);
        wpb[1023 * B_] = make_float4(wuS2[1], wd46b, wuS1[1], wd[1]);
        return;
    }

    // ===================== persistent MLP ==================================
    for (int i = threadIdx.x; i < 32 * 32; i += 256)     sW1[i] = g_W1p[i];
    for (int i = threadIdx.x; i < 16 * 8 * 32; i += 256) sW2[i] = g_W2p[i];
    for (int i = threadIdx.x; i < 4 * 32; i += 256)      sW3[i] = g_W3p[i];
    if (threadIdx.x < 256) sB1[threadIdx.x] = b1v[threadIdx.x];
    if (threadIdx.x < 64)  sB2[threadIdx.x] = b2v[threadIdx.x];
    if (threadIdx.x < 8)   sB3[threadIdx.x] = b3v[threadIdx.x];
    __syncthreads();

    int warp = threadIdx.x >> 5;
    int lane = threadIdx.x & 31;
    int g    = lane >> 2, tig = lane & 3;
    int wg   = (blockIdx.x - 1) * 8 + warp;

    for (int tile = wg; tile < 32768; tile += (NBLK - 1) * 8) {
        int r0 = tile * 16 + g;
        int r1 = r0 + 8;

        unsigned int A0, A1, A2, A3;
        {
            const float* q0p = in + r0 * 20 + 5;
            const float* q1p = in + r1 * 20 + 5;
            float x0 = q0p[2 * tig],     x1 = q0p[2 * tig + 1];
            float y0 = q1p[2 * tig],     y1 = q1p[2 * tig + 1];
            float x2 = q0p[2 * tig + 8];
            float y2 = q1p[2 * tig + 8];
            float x3 = (tig < 3) ? q0p[2 * tig + 9] : 0.0f;
            float y3 = (tig < 3) ? q1p[2 * tig + 9] : 0.0f;
            A0 = packbf(x0, x1); A1 = packbf(y0, y1);
            A2 = packbf(x2, x3); A3 = packbf(y2, y3);
        }

        // stage 1: h1 = tanh(attrs @ W1 + b1)
        unsigned int h1a[16][4];
#pragma unroll
        for (int nt = 0; nt < 32; ++nt) {
            uint2 w = sW1[nt * 32 + lane];
            float c0 = 0.f, c1 = 0.f, c2 = 0.f, c3 = 0.f;
            mma16816(c0, c1, c2, c3, A0, A1, A2, A3, w.x, w.y);
            int   n0  = nt * 8 + 2 * tig;
            float bb0 = sB1[n0], bb1 = sB1[n0 + 1];
            c0 = tanhA(c0 + bb0); c1 = tanhA(c1 + bb1);
            c2 = tanhA(c2 + bb0); c3 = tanhA(c3 + bb1);
            h1a[nt >> 1][(nt & 1) * 2 + 0] = packbf(c0, c1);
            h1a[nt >> 1][(nt & 1) * 2 + 1] = packbf(c2, c3);
        }

        // stage 2: h2 = tanh(h1 @ W2 + b2)
        float acc[8][4];
#pragma unroll
        for (int nt = 0; nt < 8; ++nt) { acc[nt][0] = acc[nt][1] = acc[nt][2] = acc[nt][3] = 0.0f; }
#pragma unroll
        for (int kc = 0; kc < 16; ++kc) {
#pragma unroll
            for (int nt = 0; nt < 8; ++nt) {
                uint2 w = sW2[(kc * 8 + nt) * 32 + lane];
                mma16816(acc[nt][0], acc[nt][1], acc[nt][2], acc[nt][3],
                         h1a[kc][0], h1a[kc][1], h1a[kc][2], h1a[kc][3], w.x, w.y);
            }
        }
        unsigned int h2a[4][4];
#pragma unroll
        for (int nt = 0; nt < 8; ++nt) {
            int   n0  = nt * 8 + 2 * tig;
            float bb0 = sB2[n0], bb1 = sB2[n0 + 1];
            float c0 = tanhA(acc[nt][0] + bb0), c1 = tanhA(acc[nt][1] + bb1);
            float c2 = tanhA(acc[nt][2] + bb0), c3 = tanhA(acc[nt][3] + bb1);
            h2a[nt >> 1][(nt & 1) * 2 + 0] = packbf(c0, c1);
            h2a[nt >> 1][(nt & 1) * 2 + 1] = packbf(c2, c3);
        }

        // stage 3: params = sigmoid(h2 @ W3 + b3)
        float p0 = 0.f, p1 = 0.f, p2 = 0.f, p3 = 0.f;
#pragma unroll
        for (int kc = 0; kc < 4; ++kc) {
            uint2 w = sW3[kc * 32 + lane];
            mma16816(p0, p1, p2, p3, h2a[kc][0], h2a[kc][1], h2a[kc][2], h2a[kc][3], w.x, w.y);
        }
        int   n0  = 2 * tig;
        float bb0 = sB3[n0], bb1 = sB3[n0 + 1];
        p0 = sigm1(p0 + bb0);
        p1 = sigm1(p1 + bb1);
        p2 = sigm1(p2 + bb0);
        p3 = sigm1(p3 + bb1);
        *reinterpret_cast<float2*>(&g_params[r0 * 8 + n0]) = make_float2(p0, p1);
        *reinterpret_cast<float2*>(&g_params[r1 * 8 + n0]) = make_float2(p2, p3);
    }
}

// ---- final pointwise: runoff + partition (reference's swapped args!) ----------
__global__ void final_kernel(const float* __restrict__ in, float* __restrict__ out) {
    int r = blockIdx.x * 256 + threadIdx.x;     // r = b*T + t
    int b = r >> 11, t = r & 2047;
    float4 wv = g_w[(t >> 1) * B_ + b];
    float wu = (t & 1) ? wv.z : wv.x;
    float wd = (t & 1) ? wv.w : wv.y;
    float p  = in[r * 20 + 2];
    float4 q0 = *reinterpret_cast<const float4*>(&g_params[r * 8]);
    float4 q1 = *reinterpret_cast<const float4*>(&g_params[r * 8 + 4]);
    float wum = q0.x, wlm = q0.y, wdm = q0.z, bb = q0.w;
    float cc  = q1.x, k1 = q1.y, k2 = q1.z, k3 = q1.w;

    // reference calls _runoff(wu, wd, wl, p, wum, wdm, wlm, b, c)
    float wum_s = wum * 19.9f + 0.1f;
    float wlm_s = wdm * 30.0f + 60.0f;   // inner wlm <- outer wdm
    float wdm_s = wlm * 60.0f + 60.0f;   // inner wdm <- outer wlm
    float c_s   = cc * 0.19f + 0.01f;
    float b_s   = bb * 0.3f + 0.1f;
    float wt    = wum_s + wlm_s + wdm_s;
    float iwt   = __frcp_rn(wt);
    float u = wu * iwt;                  // inner wu
    float v = wd * iwt;                  // inner wl <- outer wd
    float s = c_s * u * u + b_s * v * v;
    float d = p - s;
    float runoff = heav(10.0f * d) * d;

    float k1s = k1 * 0.69f + 0.01f;
    float k2s = k2 * 0.69f + 0.01f;
    float k3s = k3 * 0.89f + 0.01f;
    float sr  = k1s * runoff;
    float itf = k2s * (runoff - sr);
    float bf  = k3s * (runoff - sr - itf);
    out[r] = sr + 0.5f * itf + 0.25f * bf;
}

extern "C" void kernel_launch(void* const* d_in, const int* in_sizes, int n_in,
                              void* d_out, int out_size) {
    const float* in  = (const float*)d_in[0];
    const float* w1  = (const float*)d_in[1];
    const float* b1  = (const float*)d_in[2];
    const float* w2  = (const float*)d_in[3];
    const float* b2  = (const float*)d_in[4];
    const float* w3  = (const float*)d_in[5];
    const float* b3  = (const float*)d_in[6];
    float* out = (float*)d_out;
    prep_kernel<<<2049, 256>>>(in, w1, w2, w3);
    main_kernel<<<NBLK, 256>>>(in, b1, b2, b3);
    final_kernel<<<2048, 256>>>(in, out);
}